// round 3
// baseline (speedup 1.0000x reference)
#include <cuda_runtime.h>
#include <cuda_fp16.h>
#include <cstdint>

// Problem-shape maxima (S=128 segments, lengths in [1024,3072])
#define NMAX 393216
#define S_MAX 128

__device__ float g_y[NMAX];
__device__ float g_z[NMAX];
__device__ float4 g_segp[S_MAX];
__device__ int   g_offv[S_MAX];
__device__ float g_part[S_MAX * 4 * 256];

// ---------------------------------------------------------------------------
// Kernel 1: fused GEMM (x[128-row tile] @ W1, fp16 HMMA, fp32 accum) + head:
//   t = tanh(u + b1);  y = t@W2[:,0] + b2[0];  z = t@W2[:,1] + b2[1]
// Writes only y,z per row.
// ---------------------------------------------------------------------------
#define XST 72    // x tile SMEM stride (halves): 64 + 8 pad -> conflict-free frags
#define WST 264   // W1 SMEM stride (halves): 256 + 8 pad
#define SMEM_K1 (128*XST*2 + 128*WST*2 + 128*4 + 256*4)

__global__ __launch_bounds__(256) void gemm_head_kernel(
    const float* __restrict__ x, const float* __restrict__ W1,
    const float* __restrict__ b1, const float* __restrict__ W2,
    const float* __restrict__ b2, int N)
{
    extern __shared__ char smem[];
    half*  xs  = (half*)smem;                                   // [128][XST]
    half*  w1s = (half*)(smem + 128 * XST * 2);                  // [128 n][WST k]
    float* sb1 = (float*)(smem + 128 * XST * 2 + 128 * WST * 2); // [128]
    float* sw2 = sb1 + 128;                                      // [256] (h-major, 2 per h)

    const int tid  = threadIdx.x;
    const int lane = tid & 31;
    const int w    = tid >> 5;

    // Stage W1 transposed (n-major, k contiguous) as fp16
    for (int idx = tid; idx < 256 * 128; idx += 256) {
        int k = idx >> 7, h = idx & 127;
        w1s[h * WST + k] = __float2half(W1[idx]);
    }
    if (tid < 128) sb1[tid] = b1[tid];
    sw2[tid] = W2[tid];   // 256 entries, 256 threads

    float acc[16][4];
    #pragma unroll
    for (int i = 0; i < 16; i++) { acc[i][0]=0.f; acc[i][1]=0.f; acc[i][2]=0.f; acc[i][3]=0.f; }

    const int rowBase = blockIdx.x * 128;
    const int rA = lane >> 2;          // fragment row group 0..7
    const int qq = (lane & 3) * 2;     // fragment k offset 0,2,4,6

    for (int kc = 0; kc < 256; kc += 64) {
        __syncthreads();
        // Stage x tile: 128 rows x 64 k, fp32 -> fp16, coalesced float4
        #pragma unroll
        for (int i = 0; i < 8; i++) {
            int idx = tid + i * 256;            // 0..2047
            int r = idx >> 4, q = idx & 15;     // row, float4 index within chunk
            long grow = rowBase + r;
            float4 v = make_float4(0.f, 0.f, 0.f, 0.f);
            if (grow < N) v = ((const float4*)x)[grow * 64 + (kc >> 2) + q];
            half2* dst = (half2*)(xs + r * XST + q * 4);
            dst[0] = __floats2half2_rn(v.x, v.y);
            dst[1] = __floats2half2_rn(v.z, v.w);
        }
        __syncthreads();

        #pragma unroll
        for (int ks = 0; ks < 64; ks += 16) {
            uint32_t a0 = *(const uint32_t*)(xs + (w*16 + rA    ) * XST + ks + qq);
            uint32_t a1 = *(const uint32_t*)(xs + (w*16 + rA + 8) * XST + ks + qq);
            uint32_t a2 = *(const uint32_t*)(xs + (w*16 + rA    ) * XST + ks + qq + 8);
            uint32_t a3 = *(const uint32_t*)(xs + (w*16 + rA + 8) * XST + ks + qq + 8);
            #pragma unroll
            for (int nt = 0; nt < 16; nt++) {
                uint32_t bb0 = *(const uint32_t*)(w1s + (nt*8 + rA) * WST + kc + ks + qq);
                uint32_t bb1 = *(const uint32_t*)(w1s + (nt*8 + rA) * WST + kc + ks + qq + 8);
                asm volatile(
                    "mma.sync.aligned.m16n8k16.row.col.f32.f16.f16.f32 "
                    "{%0,%1,%2,%3}, {%4,%5,%6,%7}, {%8,%9}, {%0,%1,%2,%3};"
                    : "+f"(acc[nt][0]), "+f"(acc[nt][1]), "+f"(acc[nt][2]), "+f"(acc[nt][3])
                    : "r"(a0), "r"(a1), "r"(a2), "r"(a3), "r"(bb0), "r"(bb1));
            }
        }
    }

    // Epilogue: tanh + H->2 projection, reduce across quad (lane&3)
    float y0 = 0.f, z0 = 0.f, y1 = 0.f, z1 = 0.f;
    #pragma unroll
    for (int nt = 0; nt < 16; nt++) {
        #pragma unroll
        for (int j = 0; j < 2; j++) {
            int h = nt * 8 + qq + j;
            float bb = sb1[h], wa = sw2[2*h], wb = sw2[2*h + 1];
            float t0 = tanhf(acc[nt][j] + bb);
            y0 += t0 * wa; z0 += t0 * wb;
            float t1 = tanhf(acc[nt][2 + j] + bb);
            y1 += t1 * wa; z1 += t1 * wb;
        }
    }
    #pragma unroll
    for (int o = 1; o < 4; o <<= 1) {
        y0 += __shfl_xor_sync(0xffffffff, y0, o);
        z0 += __shfl_xor_sync(0xffffffff, z0, o);
        y1 += __shfl_xor_sync(0xffffffff, y1, o);
        z1 += __shfl_xor_sync(0xffffffff, z1, o);
    }
    if ((lane & 3) == 0) {
        float B20 = __ldg(b2), B21 = __ldg(b2 + 1);
        int gr0 = rowBase + w * 16 + rA;
        int gr1 = gr0 + 8;
        if (gr0 < N) { g_y[gr0] = y0 + B20; g_z[gr0] = z0 + B21; }
        if (gr1 < N) { g_y[gr1] = y1 + B20; g_z[gr1] = z1 + B21; }
    }
}

// ---------------------------------------------------------------------------
// Kernel 2: per-segment stats: ymax -> (wsum, sum xpos*w, sum z) -> mu, sd,
// then psum of gaussian pdf (index-only, no memory reads).
// ---------------------------------------------------------------------------
__global__ __launch_bounds__(256) void seg_stats_kernel(const int* __restrict__ lengths)
{
    __shared__ float sred[256];
    __shared__ float sbc[3];
    __shared__ int soff;
    const int s = blockIdx.x, tid = threadIdx.x;

    if (tid == 0) { int o = 0; for (int i = 0; i < s; i++) o += lengths[i]; soff = o; }
    __syncthreads();
    const int off = soff;
    const int len = lengths[s];
    const float invlen = 1.0f / (float)len;

    // pass 1: ymax
    float m = -1e30f;
    for (int i = tid; i < len; i += 256) m = fmaxf(m, g_y[off + i]);
    sred[tid] = m; __syncthreads();
    for (int o = 128; o > 0; o >>= 1) { if (tid < o) sred[tid] = fmaxf(sred[tid], sred[tid+o]); __syncthreads(); }
    const float ymax = sred[0]; __syncthreads();

    // pass 2: wsum, sum(xpos*w), sum(z)
    float wsum = 0.f, wx = 0.f, zs = 0.f;
    for (int i = tid; i < len; i += 256) {
        float wv = expf(g_y[off + i] - ymax);
        wsum += wv;
        wx   += wv * ((float)(i + 1) * invlen);
        zs   += g_z[off + i];
    }
    sred[tid] = wsum; __syncthreads();
    for (int o = 128; o > 0; o >>= 1) { if (tid < o) sred[tid] += sred[tid+o]; __syncthreads(); }
    if (tid == 0) sbc[0] = sred[0];
    __syncthreads();
    sred[tid] = wx; __syncthreads();
    for (int o = 128; o > 0; o >>= 1) { if (tid < o) sred[tid] += sred[tid+o]; __syncthreads(); }
    if (tid == 0) sbc[1] = sred[0];
    __syncthreads();
    sred[tid] = zs; __syncthreads();
    for (int o = 128; o > 0; o >>= 1) { if (tid < o) sred[tid] += sred[tid+o]; __syncthreads(); }
    if (tid == 0) sbc[2] = sred[0];
    __syncthreads();

    const float mu = sbc[1] / sbc[0];
    const float v  = sbc[2] * invlen;
    const float sd = (v > 20.f) ? v : log1pf(expf(v));   // softplus
    const float invsd = 1.0f / sd;

    // pass 3: psum (pure arithmetic)
    float ps = 0.f;
    for (int i = tid; i < len; i += 256) {
        float xp = (float)(i + 1) * invlen;
        float d = (xp - mu) * invsd;
        ps += expf(-0.5f * d * d);
    }
    sred[tid] = ps; __syncthreads();
    for (int o = 128; o > 0; o >>= 1) { if (tid < o) sred[tid] += sred[tid+o]; __syncthreads(); }
    if (tid == 0) {
        float psum = sred[0] * (0.3989422804014327f * invsd);
        g_segp[s] = make_float4(mu, sd, psum, 0.f);
        g_offv[s] = off;
    }
}

// ---------------------------------------------------------------------------
// Kernel 3: attn per row (written to output) + per-chunk partial of
// out = seg_sum(attn * x). Grid: (chunk 0..3, segment). Deterministic partials.
// ---------------------------------------------------------------------------
__global__ __launch_bounds__(256) void attn_out_kernel(
    const float* __restrict__ x, const int* __restrict__ lengths,
    float* __restrict__ attn_out)
{
    __shared__ float sattn[256];
    const int s = blockIdx.y, ch = blockIdx.x;
    const int tid = threadIdx.x;
    const int len = lengths[s];
    const int off = g_offv[s];
    const float4 p = g_segp[s];
    const float mu = p.x, sd = p.y, psum = p.z;
    const float invsd = 1.0f / sd;
    const float invlen = 1.0f / (float)len;
    const float coef = 0.3989422804014327f * invsd / (psum + 0.001f);

    float acc = 0.f;
    const int r0 = ch * 768;
    for (int tb = 0; tb < 768; tb += 256) {
        int rbase = r0 + tb;
        if (rbase >= len) break;
        int r = rbase + tid;
        float a = 0.f;
        if (r < len) {
            float xp = (float)(r + 1) * invlen;
            float d = (xp - mu) * invsd;
            a = expf(-0.5f * d * d) * coef;
            attn_out[off + r] = a;
        }
        sattn[tid] = a;
        __syncthreads();
        int nrows = min(256, len - rbase);
        const float* xp_ = x + (size_t)(off + rbase) * 256 + tid;
        if (nrows == 256) {
            #pragma unroll 8
            for (int j = 0; j < 256; j++) acc += sattn[j] * xp_[(size_t)j * 256];
        } else {
            for (int j = 0; j < nrows; j++) acc += sattn[j] * xp_[(size_t)j * 256];
        }
        __syncthreads();
    }
    g_part[(s * 4 + ch) * 256 + tid] = acc;
}

// ---------------------------------------------------------------------------
// Kernel 4: reduce the 4 chunk partials -> out[s][c]
// ---------------------------------------------------------------------------
__global__ void finalize_kernel(float* __restrict__ out)
{
    const int s = blockIdx.x, c = threadIdx.x;
    float v = g_part[(s*4 + 0)*256 + c] + g_part[(s*4 + 1)*256 + c]
            + g_part[(s*4 + 2)*256 + c] + g_part[(s*4 + 3)*256 + c];
    out[s * 256 + c] = v;
}

// ---------------------------------------------------------------------------
extern "C" void kernel_launch(void* const* d_in, const int* in_sizes, int n_in,
                              void* d_out, int out_size)
{
    const float* x       = (const float*)d_in[0];
    const int*   lengths = (const int*)  d_in[1];
    const float* W1      = (const float*)d_in[2];
    const float* b1      = (const float*)d_in[3];
    const float* W2      = (const float*)d_in[4];
    const float* b2      = (const float*)d_in[5];

    const int N = in_sizes[0] / 256;
    const int S = in_sizes[1];

    float* out  = (float*)d_out;             // (S, 256)
    float* attn = out + (size_t)S * 256;     // (N, 1)

    cudaFuncSetAttribute(gemm_head_kernel,
                         cudaFuncAttributeMaxDynamicSharedMemorySize, SMEM_K1);

    int tiles = (N + 127) / 128;
    gemm_head_kernel<<<tiles, 256, SMEM_K1>>>(x, W1, b1, W2, b2, N);
    seg_stats_kernel<<<S, 256>>>(lengths);
    attn_out_kernel<<<dim3(4, S), 256>>>(x, lengths, attn);
    finalize_kernel<<<S, 256>>>(out);
}

// round 4
// speedup vs baseline: 1.4920x; 1.4920x over previous
#include <cuda_runtime.h>
#include <cuda_fp16.h>
#include <cstdint>

// Problem-shape maxima (S=128 segments, lengths in [1024,3072])
#define NMAX 393216
#define S_MAX 128

__device__ float g_y[NMAX];
__device__ float g_z[NMAX];
__device__ float4 g_segp[S_MAX];
__device__ int   g_offv[S_MAX];
__device__ float g_part[S_MAX * 4 * 256];

__device__ __forceinline__ float tanh_approx(float v) {
    float r;
    asm("tanh.approx.f32 %0, %1;" : "=f"(r) : "f"(v));
    return r;
}

// ---------------------------------------------------------------------------
// Kernel 1 (v2): persistent, pipelined fused GEMM + head.
//   512 threads: warps 0-7 compute h[0:64), warps 8-15 compute h[64:128)
//   for the same 128-row tile. Register-prefetch of the next 64-k chunk is
//   issued before the MMA phase so DRAM latency hides under tensor work.
//   Epilogue: MUFU tanh + H->2 projection + quad shuffle + cross-half smem add.
// ---------------------------------------------------------------------------
#define XST 72    // x tile SMEM stride (halves): 64 + 8 pad -> conflict-free
#define WST 264   // W1 SMEM stride (halves): 256 + 8 pad
#define SMEM_K1 (128*XST*2 + 128*WST*2 + 128*4 + 256*4 + 128*8)

__global__ __launch_bounds__(512) void gemm_head_kernel(
    const float* __restrict__ x, const float* __restrict__ W1,
    const float* __restrict__ b1, const float* __restrict__ W2,
    const float* __restrict__ b2, int N, int ntiles)
{
    extern __shared__ char smem[];
    half*   xs  = (half*)smem;                                    // [128][XST]
    half*   w1s = (half*)(smem + 128 * XST * 2);                  // [128 h][WST k]
    float*  sb1 = (float*)(smem + 128 * XST * 2 + 128 * WST * 2); // [128]
    float*  sw2 = sb1 + 128;                                      // [256]
    float2* sEp = (float2*)(sw2 + 256);                           // [128] cross-half y,z

    const int tid  = threadIdx.x;
    const int lane = tid & 31;
    const int w    = tid >> 5;       // 0..15
    const int wa   = w & 7;          // row-tile warp (rows wa*16..wa*16+15)
    const int hb   = (w >> 3) * 8;   // h-tile base (in units of 8 columns)

    // Stage W1 transposed (h-major, k contiguous) as fp16 — once per block
    for (int idx = tid; idx < 256 * 128; idx += 512) {
        int k = idx >> 7, h = idx & 127;
        w1s[h * WST + k] = __float2half(W1[idx]);
    }
    if (tid < 128) sb1[tid] = b1[tid];
    if (tid < 256) sw2[tid] = W2[tid];
    __syncthreads();

    const int rA = lane >> 2;          // fragment row group 0..7
    const int qq = (lane & 3) * 2;     // fragment k offset 0,2,4,6
    const float B20 = __ldg(b2), B21 = __ldg(b2 + 1);
    const int stride = gridDim.x;
    const float4* __restrict__ x4 = (const float4*)x;

    float4 pf[4];

    // prefetch chunk 0 of first tile
    int t = blockIdx.x;
    if (t < ntiles) {
        int rowBase = t * 128;
        #pragma unroll
        for (int i = 0; i < 4; i++) {
            int idx = tid + i * 512;
            int r = idx >> 4, q = idx & 15;
            int grow = rowBase + r;
            pf[i] = (grow < N) ? x4[(size_t)grow * 64 + q]
                               : make_float4(0.f, 0.f, 0.f, 0.f);
        }
    }

    while (t < ntiles) {
        const int rowBase = t * 128;
        float acc[8][4];
        #pragma unroll
        for (int i = 0; i < 8; i++) {
            acc[i][0] = 0.f; acc[i][1] = 0.f; acc[i][2] = 0.f; acc[i][3] = 0.f;
        }

        #pragma unroll
        for (int kc = 0; kc < 4; kc++) {
            __syncthreads();   // previous chunk fully consumed
            // store prefetched chunk (fp32 -> fp16)
            #pragma unroll
            for (int i = 0; i < 4; i++) {
                int idx = tid + i * 512;
                int r = idx >> 4, q = idx & 15;
                half2* dst = (half2*)(xs + r * XST + q * 4);
                dst[0] = __floats2half2_rn(pf[i].x, pf[i].y);
                dst[1] = __floats2half2_rn(pf[i].z, pf[i].w);
            }
            // prefetch next chunk (this tile, or chunk 0 of the next tile)
            int nt_ = t, nkc = kc + 1;
            if (kc == 3) { nt_ = t + stride; nkc = 0; }
            if (nt_ < ntiles) {
                int rb2 = nt_ * 128;
                #pragma unroll
                for (int i = 0; i < 4; i++) {
                    int idx = tid + i * 512;
                    int r = idx >> 4, q = idx & 15;
                    int grow = rb2 + r;
                    pf[i] = (grow < N) ? x4[(size_t)grow * 64 + nkc * 16 + q]
                                       : make_float4(0.f, 0.f, 0.f, 0.f);
                }
            }
            __syncthreads();   // xs visible

            #pragma unroll
            for (int ks = 0; ks < 64; ks += 16) {
                uint32_t a0 = *(const uint32_t*)(xs + (wa*16 + rA    ) * XST + ks + qq);
                uint32_t a1 = *(const uint32_t*)(xs + (wa*16 + rA + 8) * XST + ks + qq);
                uint32_t a2 = *(const uint32_t*)(xs + (wa*16 + rA    ) * XST + ks + qq + 8);
                uint32_t a3 = *(const uint32_t*)(xs + (wa*16 + rA + 8) * XST + ks + qq + 8);
                #pragma unroll
                for (int nt = 0; nt < 8; nt++) {
                    const half* bp = w1s + ((hb + nt)*8 + rA) * WST + kc*64 + ks + qq;
                    uint32_t bb0 = *(const uint32_t*)(bp);
                    uint32_t bb1 = *(const uint32_t*)(bp + 8);
                    asm volatile(
                        "mma.sync.aligned.m16n8k16.row.col.f32.f16.f16.f32 "
                        "{%0,%1,%2,%3}, {%4,%5,%6,%7}, {%8,%9}, {%0,%1,%2,%3};"
                        : "+f"(acc[nt][0]), "+f"(acc[nt][1]), "+f"(acc[nt][2]), "+f"(acc[nt][3])
                        : "r"(a0), "r"(a1), "r"(a2), "r"(a3), "r"(bb0), "r"(bb1));
                }
            }
        }

        // Epilogue: tanh (MUFU) + H->2 projection; quad reduce; cross-half add
        float y0 = 0.f, z0 = 0.f, y1 = 0.f, z1 = 0.f;
        #pragma unroll
        for (int nt = 0; nt < 8; nt++) {
            #pragma unroll
            for (int j = 0; j < 2; j++) {
                int h = (hb + nt) * 8 + qq + j;
                float bb = sb1[h], wva = sw2[2*h], wvb = sw2[2*h + 1];
                float t0 = tanh_approx(acc[nt][j] + bb);
                y0 += t0 * wva; z0 += t0 * wvb;
                float t1 = tanh_approx(acc[nt][2 + j] + bb);
                y1 += t1 * wva; z1 += t1 * wvb;
            }
        }
        #pragma unroll
        for (int o = 1; o < 4; o <<= 1) {
            y0 += __shfl_xor_sync(0xffffffff, y0, o);
            z0 += __shfl_xor_sync(0xffffffff, z0, o);
            y1 += __shfl_xor_sync(0xffffffff, y1, o);
            z1 += __shfl_xor_sync(0xffffffff, z1, o);
        }
        __syncthreads();  // sEp reuse safe vs previous tile
        if (w >= 8 && (lane & 3) == 0) {
            sEp[wa*16 + rA    ] = make_float2(y0, z0);
            sEp[wa*16 + rA + 8] = make_float2(y1, z1);
        }
        __syncthreads();
        if (w < 8 && (lane & 3) == 0) {
            float2 e0 = sEp[wa*16 + rA];
            float2 e1 = sEp[wa*16 + rA + 8];
            int gr0 = rowBase + wa*16 + rA;
            int gr1 = gr0 + 8;
            if (gr0 < N) { g_y[gr0] = y0 + e0.x + B20; g_z[gr0] = z0 + e0.y + B21; }
            if (gr1 < N) { g_y[gr1] = y1 + e1.x + B20; g_z[gr1] = z1 + e1.y + B21; }
        }
        t += stride;
    }
}

// ---------------------------------------------------------------------------
// Kernel 2: per-segment stats: ymax -> (wsum, sum xpos*w, sum z) -> mu, sd,
// then psum of gaussian pdf (index-only, no memory reads).
// ---------------------------------------------------------------------------
__global__ __launch_bounds__(256) void seg_stats_kernel(const int* __restrict__ lengths)
{
    __shared__ float sred[256];
    __shared__ float sbc[3];
    __shared__ int soff;
    const int s = blockIdx.x, tid = threadIdx.x;

    if (tid == 0) { int o = 0; for (int i = 0; i < s; i++) o += lengths[i]; soff = o; }
    __syncthreads();
    const int off = soff;
    const int len = lengths[s];
    const float invlen = 1.0f / (float)len;

    float m = -1e30f;
    for (int i = tid; i < len; i += 256) m = fmaxf(m, g_y[off + i]);
    sred[tid] = m; __syncthreads();
    for (int o = 128; o > 0; o >>= 1) { if (tid < o) sred[tid] = fmaxf(sred[tid], sred[tid+o]); __syncthreads(); }
    const float ymax = sred[0]; __syncthreads();

    float wsum = 0.f, wx = 0.f, zs = 0.f;
    for (int i = tid; i < len; i += 256) {
        float wv = expf(g_y[off + i] - ymax);
        wsum += wv;
        wx   += wv * ((float)(i + 1) * invlen);
        zs   += g_z[off + i];
    }
    sred[tid] = wsum; __syncthreads();
    for (int o = 128; o > 0; o >>= 1) { if (tid < o) sred[tid] += sred[tid+o]; __syncthreads(); }
    if (tid == 0) sbc[0] = sred[0];
    __syncthreads();
    sred[tid] = wx; __syncthreads();
    for (int o = 128; o > 0; o >>= 1) { if (tid < o) sred[tid] += sred[tid+o]; __syncthreads(); }
    if (tid == 0) sbc[1] = sred[0];
    __syncthreads();
    sred[tid] = zs; __syncthreads();
    for (int o = 128; o > 0; o >>= 1) { if (tid < o) sred[tid] += sred[tid+o]; __syncthreads(); }
    if (tid == 0) sbc[2] = sred[0];
    __syncthreads();

    const float mu = sbc[1] / sbc[0];
    const float v  = sbc[2] * invlen;
    const float sd = (v > 20.f) ? v : log1pf(expf(v));   // softplus
    const float invsd = 1.0f / sd;

    float ps = 0.f;
    for (int i = tid; i < len; i += 256) {
        float xp = (float)(i + 1) * invlen;
        float d = (xp - mu) * invsd;
        ps += expf(-0.5f * d * d);
    }
    sred[tid] = ps; __syncthreads();
    for (int o = 128; o > 0; o >>= 1) { if (tid < o) sred[tid] += sred[tid+o]; __syncthreads(); }
    if (tid == 0) {
        float psum = sred[0] * (0.3989422804014327f * invsd);
        g_segp[s] = make_float4(mu, sd, psum, 0.f);
        g_offv[s] = off;
    }
}

// ---------------------------------------------------------------------------
// Kernel 3 (v2): attn per row + per-chunk partial of out = seg_sum(attn*x).
//   4 row-groups x 64 threads; each thread owns 4 columns (float4 loads),
//   giving 4+ independent FMA chains and 16B global loads.
// ---------------------------------------------------------------------------
__global__ __launch_bounds__(256) void attn_out_kernel(
    const float* __restrict__ x, const int* __restrict__ lengths,
    float* __restrict__ attn_out)
{
    __shared__ float  sattn[256];
    __shared__ float4 sred4[256];
    const int s = blockIdx.y, ch = blockIdx.x;
    const int tid = threadIdx.x;
    const int g = tid >> 6;          // row group 0..3
    const int c = tid & 63;          // float4 column index (cols 4c..4c+3)
    const int len = lengths[s];
    const int off = g_offv[s];
    const float4 p = g_segp[s];
    const float mu = p.x, invsd = 1.0f / p.y, psum = p.z;
    const float invlen = 1.0f / (float)len;
    const float coef = 0.3989422804014327f * invsd / (psum + 0.001f);

    float4 acc = make_float4(0.f, 0.f, 0.f, 0.f);
    const int r0 = ch * 768;
    for (int tb = 0; tb < 768; tb += 256) {
        int rbase = r0 + tb;
        if (rbase >= len) break;
        int r = rbase + tid;
        float a = 0.f;
        if (r < len) {
            float xp = (float)(r + 1) * invlen;
            float d = (xp - mu) * invsd;
            a = expf(-0.5f * d * d) * coef;
            attn_out[off + r] = a;
        }
        sattn[tid] = a;
        __syncthreads();
        int nrows = min(256, len - rbase);
        const float4* __restrict__ xp4 = (const float4*)(x + (size_t)(off + rbase) * 256) + c;
        int j = g;
        for (; j + 4 < nrows; j += 8) {
            float a0 = sattn[j], a1 = sattn[j + 4];
            float4 v0 = xp4[(size_t)j * 64];
            float4 v1 = xp4[(size_t)(j + 4) * 64];
            acc.x += a0 * v0.x; acc.y += a0 * v0.y; acc.z += a0 * v0.z; acc.w += a0 * v0.w;
            acc.x += a1 * v1.x; acc.y += a1 * v1.y; acc.z += a1 * v1.z; acc.w += a1 * v1.w;
        }
        for (; j < nrows; j += 4) {
            float a0 = sattn[j];
            float4 v0 = xp4[(size_t)j * 64];
            acc.x += a0 * v0.x; acc.y += a0 * v0.y; acc.z += a0 * v0.z; acc.w += a0 * v0.w;
        }
        __syncthreads();
    }
    sred4[tid] = acc;
    __syncthreads();
    if (g == 0) {
        float4 t0 = sred4[c], t1 = sred4[64 + c], t2 = sred4[128 + c], t3 = sred4[192 + c];
        float4 tot = make_float4(t0.x + t1.x + t2.x + t3.x,
                                 t0.y + t1.y + t2.y + t3.y,
                                 t0.z + t1.z + t2.z + t3.z,
                                 t0.w + t1.w + t2.w + t3.w);
        ((float4*)&g_part[(size_t)(s * 4 + ch) * 256])[c] = tot;
    }
}

// ---------------------------------------------------------------------------
// Kernel 4: reduce the 4 chunk partials -> out[s][c]
// ---------------------------------------------------------------------------
__global__ void finalize_kernel(float* __restrict__ out)
{
    const int s = blockIdx.x, c = threadIdx.x;
    float v = g_part[(s*4 + 0)*256 + c] + g_part[(s*4 + 1)*256 + c]
            + g_part[(s*4 + 2)*256 + c] + g_part[(s*4 + 3)*256 + c];
    out[s * 256 + c] = v;
}

// ---------------------------------------------------------------------------
extern "C" void kernel_launch(void* const* d_in, const int* in_sizes, int n_in,
                              void* d_out, int out_size)
{
    const float* x       = (const float*)d_in[0];
    const int*   lengths = (const int*)  d_in[1];
    const float* W1      = (const float*)d_in[2];
    const float* b1      = (const float*)d_in[3];
    const float* W2      = (const float*)d_in[4];
    const float* b2      = (const float*)d_in[5];

    const int N = in_sizes[0] / 256;
    const int S = in_sizes[1];

    float* out  = (float*)d_out;             // (S, 256)
    float* attn = out + (size_t)S * 256;     // (N, 1)

    cudaFuncSetAttribute(gemm_head_kernel,
                         cudaFuncAttributeMaxDynamicSharedMemorySize, SMEM_K1);

    int ntiles = (N + 127) / 128;
    int grid = ntiles < 148 ? ntiles : 148;
    gemm_head_kernel<<<grid, 512, SMEM_K1>>>(x, W1, b1, W2, b2, N, ntiles);
    seg_stats_kernel<<<S, 256>>>(lengths);
    attn_out_kernel<<<dim3(4, S), 256>>>(x, lengths, attn);
    finalize_kernel<<<S, 256>>>(out);
}

// round 6
// speedup vs baseline: 1.8292x; 1.2260x over previous
#include <cuda_runtime.h>
#include <cuda_fp16.h>
#include <cstdint>

// Problem-shape maxima (S=128 segments, lengths in [1024,3072])
#define NMAX 393216
#define S_MAX 128

__device__ float g_y[NMAX];
__device__ float g_z[NMAX];
__device__ float4 g_segp[S_MAX];
__device__ int   g_offv[S_MAX];
__device__ float g_part[S_MAX * 4 * 256];

__device__ __forceinline__ float tanh_approx(float v) {
    float r;
    asm("tanh.approx.f32 %0, %1;" : "=f"(r) : "f"(v));
    return r;
}

// ---------------------------------------------------------------------------
// Kernel 1 (v4): persistent fused GEMM + head, mma.sync HMMA (sm_103-portable).
//   256 threads / 8 warps, 2 blocks per SM.
//   Warps 0-3: h[0:64), warps 4-7: h[64:128); each warp owns 32 rows
//   (two m16 row groups) so every B fragment feeds 2 MMAs -> smem traffic
//   per chunk drops from 160KB to 96KB vs the 16-rows/warp version.
//   Register prefetch of the next 64-k chunk hides DRAM latency under MMAs.
// ---------------------------------------------------------------------------
#define XST 72    // x tile SMEM stride (halves): 64 + 8 pad -> conflict-free
#define WST 264   // W1 SMEM stride (halves): 256 + 8 pad
#define SMEM_K1 (128*XST*2 + 128*WST*2 + 128*4 + 256*4 + 128*8)

__global__ __launch_bounds__(256, 2) void gemm_head_kernel(
    const float* __restrict__ x, const float* __restrict__ W1,
    const float* __restrict__ b1, const float* __restrict__ W2,
    const float* __restrict__ b2, int N, int ntiles)
{
    extern __shared__ char smem[];
    half*   xs  = (half*)smem;                                    // [128][XST]
    half*   w1s = (half*)(smem + 128 * XST * 2);                  // [128 h][WST k]
    float*  sb1 = (float*)(smem + 128 * XST * 2 + 128 * WST * 2); // [128]
    float*  sw2 = sb1 + 128;                                      // [256]
    float2* sEp = (float2*)(sw2 + 256);                           // [128]

    const int tid  = threadIdx.x;
    const int lane = tid & 31;
    const int w    = tid >> 5;       // 0..7
    const int wa   = w & 3;          // row quarter: rows wa*32 .. wa*32+31
    const int hb   = (w >> 2) * 8;   // h-tile base (units of 8 columns)

    // Stage W1 transposed (h-major, k contiguous) as fp16 — once per block
    for (int idx = tid; idx < 256 * 128; idx += 256) {
        int k = idx >> 7, h = idx & 127;
        w1s[h * WST + k] = __float2half(W1[idx]);
    }
    if (tid < 128) sb1[tid] = b1[tid];
    sw2[tid] = W2[tid];
    __syncthreads();

    const int rA = lane >> 2;          // fragment row 0..7 within group
    const int qq = (lane & 3) * 2;     // fragment k offset 0,2,4,6
    const float B20 = __ldg(b2), B21 = __ldg(b2 + 1);
    const int stride = gridDim.x;
    const float4* __restrict__ x4 = (const float4*)x;
    const float4 zero4 = make_float4(0.f, 0.f, 0.f, 0.f);

    float4 pf[8];

    int t = blockIdx.x;
    // prefetch chunk 0 of first tile
    if (t < ntiles) {
        int rowBase = t * 128;
        #pragma unroll
        for (int i = 0; i < 8; i++) {
            int idx = tid + i * 256;
            int r = idx >> 4, q = idx & 15;
            int grow = rowBase + r;
            pf[i] = (grow < N) ? x4[(size_t)grow * 64 + q] : zero4;
        }
    }

    while (t < ntiles) {
        const int rowBase = t * 128;
        float acc[8][2][4];
        #pragma unroll
        for (int i = 0; i < 8; i++)
            #pragma unroll
            for (int g = 0; g < 2; g++) {
                acc[i][g][0] = 0.f; acc[i][g][1] = 0.f;
                acc[i][g][2] = 0.f; acc[i][g][3] = 0.f;
            }

        #pragma unroll
        for (int kc = 0; kc < 4; kc++) {
            __syncthreads();   // previous chunk fully consumed
            // store prefetched chunk (fp32 -> fp16)
            #pragma unroll
            for (int i = 0; i < 8; i++) {
                int idx = tid + i * 256;
                int r = idx >> 4, q = idx & 15;
                half2* dst = (half2*)(xs + r * XST + q * 4);
                dst[0] = __floats2half2_rn(pf[i].x, pf[i].y);
                dst[1] = __floats2half2_rn(pf[i].z, pf[i].w);
            }
            // prefetch next chunk (this tile, or chunk 0 of the next tile)
            int nt_ = t, nkc = kc + 1;
            if (kc == 3) { nt_ = t + stride; nkc = 0; }
            if (nt_ < ntiles) {
                int rb2 = nt_ * 128;
                #pragma unroll
                for (int i = 0; i < 8; i++) {
                    int idx = tid + i * 256;
                    int r = idx >> 4, q = idx & 15;
                    int grow = rb2 + r;
                    pf[i] = (grow < N) ? x4[(size_t)grow * 64 + nkc * 16 + q] : zero4;
                }
            }
            __syncthreads();   // xs visible

            #pragma unroll
            for (int ks = 0; ks < 64; ks += 16) {
                // A fragments for both row groups (rows wa*32 + {0,8,16,24} + rA)
                const half* ab = xs + (wa * 32 + rA) * XST + ks + qq;
                uint32_t a00 = *(const uint32_t*)(ab);
                uint32_t a01 = *(const uint32_t*)(ab +  8 * XST);
                uint32_t a02 = *(const uint32_t*)(ab + 8);
                uint32_t a03 = *(const uint32_t*)(ab +  8 * XST + 8);
                uint32_t a10 = *(const uint32_t*)(ab + 16 * XST);
                uint32_t a11 = *(const uint32_t*)(ab + 24 * XST);
                uint32_t a12 = *(const uint32_t*)(ab + 16 * XST + 8);
                uint32_t a13 = *(const uint32_t*)(ab + 24 * XST + 8);
                #pragma unroll
                for (int nt = 0; nt < 8; nt++) {
                    const half* bp = w1s + ((hb + nt) * 8 + rA) * WST + kc * 64 + ks + qq;
                    uint32_t bb0 = *(const uint32_t*)(bp);
                    uint32_t bb1 = *(const uint32_t*)(bp + 8);
                    asm volatile(
                        "mma.sync.aligned.m16n8k16.row.col.f32.f16.f16.f32 "
                        "{%0,%1,%2,%3}, {%4,%5,%6,%7}, {%8,%9}, {%0,%1,%2,%3};"
                        : "+f"(acc[nt][0][0]), "+f"(acc[nt][0][1]), "+f"(acc[nt][0][2]), "+f"(acc[nt][0][3])
                        : "r"(a00), "r"(a01), "r"(a02), "r"(a03), "r"(bb0), "r"(bb1));
                    asm volatile(
                        "mma.sync.aligned.m16n8k16.row.col.f32.f16.f16.f32 "
                        "{%0,%1,%2,%3}, {%4,%5,%6,%7}, {%8,%9}, {%0,%1,%2,%3};"
                        : "+f"(acc[nt][1][0]), "+f"(acc[nt][1][1]), "+f"(acc[nt][1][2]), "+f"(acc[nt][1][3])
                        : "r"(a10), "r"(a11), "r"(a12), "r"(a13), "r"(bb0), "r"(bb1));
                }
            }
        }

        // Epilogue: tanh (MUFU) + H->2 projection; quad reduce; cross-half add
        float yv[2][2] = {{0.f,0.f},{0.f,0.f}};
        float zv[2][2] = {{0.f,0.f},{0.f,0.f}};
        #pragma unroll
        for (int nt = 0; nt < 8; nt++) {
            #pragma unroll
            for (int j = 0; j < 2; j++) {
                int h = (hb + nt) * 8 + qq + j;
                float bb = sb1[h], wva = sw2[2*h], wvb = sw2[2*h + 1];
                #pragma unroll
                for (int g = 0; g < 2; g++) {
                    float t0 = tanh_approx(acc[nt][g][j] + bb);
                    yv[g][0] += t0 * wva; zv[g][0] += t0 * wvb;
                    float t1 = tanh_approx(acc[nt][g][2 + j] + bb);
                    yv[g][1] += t1 * wva; zv[g][1] += t1 * wvb;
                }
            }
        }
        #pragma unroll
        for (int o = 1; o < 4; o <<= 1) {
            #pragma unroll
            for (int g = 0; g < 2; g++) {
                yv[g][0] += __shfl_xor_sync(0xffffffff, yv[g][0], o);
                zv[g][0] += __shfl_xor_sync(0xffffffff, zv[g][0], o);
                yv[g][1] += __shfl_xor_sync(0xffffffff, yv[g][1], o);
                zv[g][1] += __shfl_xor_sync(0xffffffff, zv[g][1], o);
            }
        }
        __syncthreads();  // sEp reuse safe vs previous tile / xs reuse safe
        if (w >= 4 && (lane & 3) == 0) {
            #pragma unroll
            for (int g = 0; g < 2; g++) {
                sEp[wa*32 + g*16 + rA    ] = make_float2(yv[g][0], zv[g][0]);
                sEp[wa*32 + g*16 + rA + 8] = make_float2(yv[g][1], zv[g][1]);
            }
        }
        __syncthreads();
        if (w < 4 && (lane & 3) == 0) {
            #pragma unroll
            for (int g = 0; g < 2; g++) {
                float2 e0 = sEp[wa*32 + g*16 + rA];
                float2 e1 = sEp[wa*32 + g*16 + rA + 8];
                int gr0 = rowBase + wa*32 + g*16 + rA;
                int gr1 = gr0 + 8;
                if (gr0 < N) { g_y[gr0] = yv[g][0] + e0.x + B20; g_z[gr0] = zv[g][0] + e0.y + B21; }
                if (gr1 < N) { g_y[gr1] = yv[g][1] + e1.x + B20; g_z[gr1] = zv[g][1] + e1.y + B21; }
            }
        }
        t += stride;
    }
}

// ---------------------------------------------------------------------------
// Kernel 2: per-segment stats. |y| <= ||W2[:,0]||_1 ~ 11, so exp(y) is safe
// without max subtraction -> 2 passes over g_y instead of 3.
// ---------------------------------------------------------------------------
__global__ __launch_bounds__(256) void seg_stats_kernel(const int* __restrict__ lengths)
{
    __shared__ float sred[256];
    __shared__ float sbc[3];
    __shared__ int soff;
    const int s = blockIdx.x, tid = threadIdx.x;

    if (tid == 0) { int o = 0; for (int i = 0; i < s; i++) o += lengths[i]; soff = o; }
    __syncthreads();
    const int off = soff;
    const int len = lengths[s];
    const float invlen = 1.0f / (float)len;

    float wsum = 0.f, wx = 0.f, zs = 0.f;
    for (int i = tid; i < len; i += 256) {
        float wv = expf(g_y[off + i]);
        wsum += wv;
        wx   += wv * ((float)(i + 1) * invlen);
        zs   += g_z[off + i];
    }
    sred[tid] = wsum; __syncthreads();
    for (int o = 128; o > 0; o >>= 1) { if (tid < o) sred[tid] += sred[tid+o]; __syncthreads(); }
    if (tid == 0) sbc[0] = sred[0];
    __syncthreads();
    sred[tid] = wx; __syncthreads();
    for (int o = 128; o > 0; o >>= 1) { if (tid < o) sred[tid] += sred[tid+o]; __syncthreads(); }
    if (tid == 0) sbc[1] = sred[0];
    __syncthreads();
    sred[tid] = zs; __syncthreads();
    for (int o = 128; o > 0; o >>= 1) { if (tid < o) sred[tid] += sred[tid+o]; __syncthreads(); }
    if (tid == 0) sbc[2] = sred[0];
    __syncthreads();

    const float mu = sbc[1] / sbc[0];
    const float v  = sbc[2] * invlen;
    const float sd = (v > 20.f) ? v : log1pf(expf(v));   // softplus
    const float invsd = 1.0f / sd;

    float ps = 0.f;
    for (int i = tid; i < len; i += 256) {
        float xp = (float)(i + 1) * invlen;
        float d = (xp - mu) * invsd;
        ps += expf(-0.5f * d * d);
    }
    sred[tid] = ps; __syncthreads();
    for (int o = 128; o > 0; o >>= 1) { if (tid < o) sred[tid] += sred[tid+o]; __syncthreads(); }
    if (tid == 0) {
        float psum = sred[0] * (0.3989422804014327f * invsd);
        g_segp[s] = make_float4(mu, sd, psum, 0.f);
        g_offv[s] = off;
    }
}

// ---------------------------------------------------------------------------
// Kernel 3: attn per row + per-chunk partial of out = seg_sum(attn*x).
//   4 row-groups x 64 threads, float4 loads, unroll-4 (MLP=4).
// ---------------------------------------------------------------------------
__global__ __launch_bounds__(256) void attn_out_kernel(
    const float* __restrict__ x, const int* __restrict__ lengths,
    float* __restrict__ attn_out)
{
    __shared__ float  sattn[256];
    __shared__ float4 sred4[256];
    const int s = blockIdx.y, ch = blockIdx.x;
    const int tid = threadIdx.x;
    const int g = tid >> 6;
    const int c = tid & 63;
    const int len = lengths[s];
    const int off = g_offv[s];
    const float4 p = g_segp[s];
    const float mu = p.x, invsd = 1.0f / p.y, psum = p.z;
    const float invlen = 1.0f / (float)len;
    const float coef = 0.3989422804014327f * invsd / (psum + 0.001f);

    float4 acc = make_float4(0.f, 0.f, 0.f, 0.f);
    const int r0 = ch * 768;
    for (int tb = 0; tb < 768; tb += 256) {
        int rbase = r0 + tb;
        if (rbase >= len) break;
        int r = rbase + tid;
        float a = 0.f;
        if (r < len) {
            float xp = (float)(r + 1) * invlen;
            float d = (xp - mu) * invsd;
            a = expf(-0.5f * d * d) * coef;
            attn_out[off + r] = a;
        }
        sattn[tid] = a;
        __syncthreads();
        int nrows = min(256, len - rbase);
        const float4* __restrict__ xp4 = (const float4*)(x + (size_t)(off + rbase) * 256) + c;
        int j = g;
        for (; j + 12 < nrows; j += 16) {
            float a0 = sattn[j], a1 = sattn[j + 4], a2 = sattn[j + 8], a3 = sattn[j + 12];
            float4 v0 = xp4[(size_t)j * 64];
            float4 v1 = xp4[(size_t)(j + 4) * 64];
            float4 v2 = xp4[(size_t)(j + 8) * 64];
            float4 v3 = xp4[(size_t)(j + 12) * 64];
            acc.x += a0 * v0.x; acc.y += a0 * v0.y; acc.z += a0 * v0.z; acc.w += a0 * v0.w;
            acc.x += a1 * v1.x; acc.y += a1 * v1.y; acc.z += a1 * v1.z; acc.w += a1 * v1.w;
            acc.x += a2 * v2.x; acc.y += a2 * v2.y; acc.z += a2 * v2.z; acc.w += a2 * v2.w;
            acc.x += a3 * v3.x; acc.y += a3 * v3.y; acc.z += a3 * v3.z; acc.w += a3 * v3.w;
        }
        for (; j < nrows; j += 4) {
            float a0 = sattn[j];
            float4 v0 = xp4[(size_t)j * 64];
            acc.x += a0 * v0.x; acc.y += a0 * v0.y; acc.z += a0 * v0.z; acc.w += a0 * v0.w;
        }
        __syncthreads();
    }
    sred4[tid] = acc;
    __syncthreads();
    if (g == 0) {
        float4 t0 = sred4[c], t1 = sred4[64 + c], t2 = sred4[128 + c], t3 = sred4[192 + c];
        float4 tot = make_float4(t0.x + t1.x + t2.x + t3.x,
                                 t0.y + t1.y + t2.y + t3.y,
                                 t0.z + t1.z + t2.z + t3.z,
                                 t0.w + t1.w + t2.w + t3.w);
        ((float4*)&g_part[(size_t)(s * 4 + ch) * 256])[c] = tot;
    }
}

// ---------------------------------------------------------------------------
// Kernel 4: reduce the 4 chunk partials -> out[s][:]  (float4, 64 threads)
// ---------------------------------------------------------------------------
__global__ void finalize_kernel(float* __restrict__ out)
{
    const int s = blockIdx.x, c = threadIdx.x;   // 64 threads
    const float4* p = (const float4*)&g_part[(size_t)s * 4 * 256];
    float4 t0 = p[c], t1 = p[64 + c], t2 = p[128 + c], t3 = p[192 + c];
    float4 tot = make_float4(t0.x + t1.x + t2.x + t3.x,
                             t0.y + t1.y + t2.y + t3.y,
                             t0.z + t1.z + t2.z + t3.z,
                             t0.w + t1.w + t2.w + t3.w);
    ((float4*)(out + (size_t)s * 256))[c] = tot;
}

// ---------------------------------------------------------------------------
extern "C" void kernel_launch(void* const* d_in, const int* in_sizes, int n_in,
                              void* d_out, int out_size)
{
    const float* x       = (const float*)d_in[0];
    const int*   lengths = (const int*)  d_in[1];
    const float* W1      = (const float*)d_in[2];
    const float* b1      = (const float*)d_in[3];
    const float* W2      = (const float*)d_in[4];
    const float* b2      = (const float*)d_in[5];

    const int N = in_sizes[0] / 256;
    const int S = in_sizes[1];

    float* out  = (float*)d_out;             // (S, 256)
    float* attn = out + (size_t)S * 256;     // (N, 1)

    cudaFuncSetAttribute(gemm_head_kernel,
                         cudaFuncAttributeMaxDynamicSharedMemorySize, SMEM_K1);

    int ntiles = (N + 127) / 128;
    int grid = ntiles < 296 ? ntiles : 296;   // 2 blocks/SM persistent
    gemm_head_kernel<<<grid, 256, SMEM_K1>>>(x, W1, b1, W2, b2, N, ntiles);
    seg_stats_kernel<<<S, 256>>>(lengths);
    attn_out_kernel<<<dim3(4, S), 256>>>(x, lengths, attn);
    finalize_kernel<<<S, 64>>>(out);
}